// round 14
// baseline (speedup 1.0000x reference)
#include <cuda_runtime.h>
#include <cuda_fp16.h>
#include <stdint.h>
#include <math.h>

// ---------------- static problem shapes ----------------
#define BB    8
#define HH    56
#define WW    56
#define NN    (HH*WW)        // 3136
#define CC    256
#define NHEAD 8
#define CH    32
#define BN_TOT (BB*NN)       // 25088
#define QKVW  768
#define MH    1024
#define KSEG  98             // 32-token segments

// ---------------- scratch ----------------
__device__ __align__(16) __half g_x1h [BN_TOT*CC];
__device__ __align__(16) __half g_x2h [BN_TOT*CC];
__device__ __align__(16) __half g_qh  [BN_TOT*CC];
__device__ __align__(16) __half g_kh  [BN_TOT*CC];   // holds exp(k)
__device__ __align__(16) __half g_vh  [BN_TOT*CC];
__device__ __align__(16) __half g_curh[BN_TOT*CC];
__device__ __align__(16) __half g_atth[BN_TOT*CC];
__device__ __align__(16) __half g_hidh[BN_TOT*MH];
__device__ __align__(16) __half g_wth [786432];
__device__ float  g_kv  [64*CH*CH];
__device__ float  g_da  [BB*CC];
__device__ float  g_kvp [KSEG*64*CH*CH];
__device__ float  g_ksp [KSEG*64*CH];

// ---------------- helpers ----------------
__device__ __forceinline__ uint32_t smem_u32(const void* p){
    uint32_t a; asm("{.reg .u64 t; cvta.to.shared.u64 t, %1; cvt.u32.u64 %0, t;}":"=r"(a):"l"(p)); return a;
}
__device__ __forceinline__ void cp_async16(uint32_t dst, const void* src){
    asm volatile("cp.async.cg.shared.global [%0], [%1], 16;"::"r"(dst),"l"(src):"memory");
}
__device__ __forceinline__ void cp_commit(){ asm volatile("cp.async.commit_group;":::"memory"); }
template<int N> __device__ __forceinline__ void cp_wait(){ asm volatile("cp.async.wait_group %0;"::"n"(N):"memory"); }

__device__ __forceinline__ void ldsm4(uint32_t* r, uint32_t addr){
    asm volatile("ldmatrix.sync.aligned.m8n8.x4.shared.b16 {%0,%1,%2,%3}, [%4];"
        :"=r"(r[0]),"=r"(r[1]),"=r"(r[2]),"=r"(r[3]):"r"(addr));
}
__device__ __forceinline__ void ldsm4t(uint32_t* r, uint32_t addr){
    asm volatile("ldmatrix.sync.aligned.m8n8.x4.trans.shared.b16 {%0,%1,%2,%3}, [%4];"
        :"=r"(r[0]),"=r"(r[1]),"=r"(r[2]),"=r"(r[3]):"r"(addr));
}
__device__ __forceinline__ void mma_f16(float* d, const uint32_t* a, const uint32_t* b){
    asm volatile(
        "mma.sync.aligned.m16n8k16.row.col.f32.f16.f16.f32 "
        "{%0,%1,%2,%3}, {%4,%5,%6,%7}, {%8,%9}, {%0,%1,%2,%3};"
        : "+f"(d[0]),"+f"(d[1]),"+f"(d[2]),"+f"(d[3])
        : "r"(a[0]),"r"(a[1]),"r"(a[2]),"r"(a[3]),"r"(b[0]),"r"(b[1]));
}

__device__ __forceinline__ uint32_t aoff(int r, int q){
    return (uint32_t)((r << 7) + (((q ^ (r & 7)) & 7) << 4));
}
template<int CB>
__device__ __forceinline__ uint32_t boff(int k, int c){
    if (CB == 16) return (uint32_t)((k << 8) + ((((c & 8) | ((c & 7) ^ (k & 7)))) << 4));
    else          return (uint32_t)((k << 7) + ((((c ^ (k & 7)) & 7)) << 4));
}

// ---------------- weight fp32 -> half converters ----------------
__global__ void f2h_one(const float* __restrict__ src, __half* __restrict__ dst){
    int i = (blockIdx.x * blockDim.x + threadIdx.x) * 4;
    float4 v = *(const float4*)(src + i);
    __half2 h0 = __floats2half2_rn(v.x, v.y);
    __half2 h1 = __floats2half2_rn(v.z, v.w);
    *(uint2*)(dst + i) = make_uint2(*(uint32_t*)&h0, *(uint32_t*)&h1);
}
__global__ void f2h_rest(const float* __restrict__ b, const float* __restrict__ c,
                         const float* __restrict__ d, __half* __restrict__ dst){
    int i = (blockIdx.x * blockDim.x + threadIdx.x) * 4;   // 0..589823
    const float* src; int off;
    if      (i < 65536)  { src = b; off = 0; }
    else if (i < 327680) { src = c; off = 65536; }
    else                 { src = d; off = 327680; }
    float4 v = *(const float4*)(src + (i - off));
    __half2 h0 = __floats2half2_rn(v.x, v.y);
    __half2 h1 = __floats2half2_rn(v.z, v.w);
    *(uint2*)(dst + 196608 + i) = make_uint2(*(uint32_t*)&h0, *(uint32_t*)&h1);
}

// ---------------- CPE dw3x3 + residual + LN1, 8-token tiles ----------------
__global__ __launch_bounds__(128)
void cpe_ln1_kernel(const float* __restrict__ x,
                    const float* __restrict__ cpe_w,
                    const float* __restrict__ cpe_b,
                    const float* __restrict__ ln_g,
                    const float* __restrict__ ln_b, int blk0) {
    int blk = blk0 + blockIdx.x;
    int b   = blk / (NN / 8);
    int rem = blk % (NN / 8);
    int hh  = rem / (WW / 8);
    int ww0 = (rem % (WW / 8)) * 8;
    int t   = threadIdx.x;
    int c0  = t * 2;

    const float* xb = x + (size_t)b * NN * CC + c0;
    const float* w0 = cpe_w + c0 * 9;
    const float* w1 = w0 + 9;
    float w0r[9], w1r[9];
    #pragma unroll
    for (int j = 0; j < 9; j++) { w0r[j] = w0[j]; w1r[j] = w1[j]; }

    float cv0[8], cv1[8];
    float bias0 = cpe_b[c0], bias1 = cpe_b[c0 + 1];
    #pragma unroll
    for (int tok = 0; tok < 8; tok++) { cv0[tok] = bias0; cv1[tok] = bias1; }
    float xc0[8], xc1[8];

    #pragma unroll
    for (int dy = 0; dy < 3; dy++) {
        int y = hh - 1 + dy;
        bool yok = (unsigned)y < HH;
        #pragma unroll
        for (int xx = 0; xx < 10; xx++) {
            int gx = ww0 - 1 + xx;
            float2 xv = make_float2(0.f, 0.f);
            if (yok && (unsigned)gx < WW)
                xv = *(const float2*)(xb + (size_t)(y * WW + gx) * CC);
            if (dy == 1 && xx >= 1 && xx <= 8) { xc0[xx - 1] = xv.x; xc1[xx - 1] = xv.y; }
            #pragma unroll
            for (int tok = 0; tok < 8; tok++) {
                int j = xx - tok;
                if (j < 0 || j >= 3) continue;
                cv0[tok] += xv.x * w0r[dy * 3 + j];
                cv1[tok] += xv.y * w1r[dy * 3 + j];
            }
        }
    }

    size_t row0 = (size_t)b * NN + hh * WW + ww0;
    __shared__ float s1[128][9];
    __shared__ float s2[128][9];
    #pragma unroll
    for (int tok = 0; tok < 8; tok++) {
        cv0[tok] += xc0[tok];
        cv1[tok] += xc1[tok];
        *(__half2*)(g_x1h + (row0 + tok) * CC + c0) = __floats2half2_rn(cv0[tok], cv1[tok]);
        s1[t][tok] = cv0[tok] + cv1[tok];
        s2[t][tok] = cv0[tok] * cv0[tok] + cv1[tok] * cv1[tok];
    }
    __syncthreads();
    for (int off = 64; off > 0; off >>= 1) {
        if (t < off) {
            #pragma unroll
            for (int tok = 0; tok < 8; tok++) {
                s1[t][tok] += s1[t + off][tok];
                s2[t][tok] += s2[t + off][tok];
            }
        }
        __syncthreads();
    }
    float g0 = ln_g[c0], g1 = ln_g[c0 + 1];
    float bb0 = ln_b[c0], bb1 = ln_b[c0 + 1];
    #pragma unroll
    for (int tok = 0; tok < 8; tok++) {
        float mean = s1[0][tok] * (1.0f / CC);
        float var  = s2[0][tok] * (1.0f / CC) - mean * mean;
        float inv  = rsqrtf(var + 1e-5f);
        float o0 = (cv0[tok] - mean) * inv * g0 + bb0;
        float o1 = (cv1[tok] - mean) * inv * g1 + bb1;
        *(__half2*)(g_curh + (row0 + tok) * CC + c0) = __floats2half2_rn(o0, o1);
    }
}

// ---------------- LN2 (reads half x2), 2 rows per block ----------------
__global__ __launch_bounds__(256)
void ln2_kernel(const float* __restrict__ ln_g,
                const float* __restrict__ ln_b, int bn0) {
    int t   = threadIdx.x;
    int sub = t >> 7;
    int tt  = t & 127;
    int bn  = bn0 + blockIdx.x * 2 + sub;
    int c0  = tt * 2;
    float2 xv = __half22float2(*(const __half2*)(g_x2h + (size_t)bn * CC + c0));
    __shared__ float s1[2][128];
    __shared__ float s2[2][128];
    s1[sub][tt] = xv.x + xv.y;
    s2[sub][tt] = xv.x * xv.x + xv.y * xv.y;
    __syncthreads();
    for (int off = 64; off > 0; off >>= 1) {
        if (tt < off) {
            s1[sub][tt] += s1[sub][tt + off];
            s2[sub][tt] += s2[sub][tt + off];
        }
        __syncthreads();
    }
    float mean = s1[sub][0] * (1.0f / CC);
    float var  = s2[sub][0] * (1.0f / CC) - mean * mean;
    float inv  = rsqrtf(var + 1e-5f);
    float o0 = (xv.x - mean) * inv * ln_g[c0]     + ln_b[c0];
    float o1 = (xv.y - mean) * inv * ln_g[c0 + 1] + ln_b[c0 + 1];
    *(__half2*)(g_curh + (size_t)bn * CC + c0) = __floats2half2_rn(o0, o1);
}

// ---------------- fp16 tensor-core GEMM ----------------
// EPI 2: half C = gelu(acc+bias)
// EPI 3: qkv split all-half -> q, exp(k), v
// EPI 4: half C = acc + bias + half-res          (proj -> x2h)
// EPI 5: fp32 C = acc + bias + half-res          (fc2 -> out)
template <int EPI, int BN>
__global__ __launch_bounds__(256, 2)
void gemm_h(const __half* __restrict__ A, const __half* __restrict__ B,
            void* __restrict__ Cv, int M, int Nc, int K,
            const float* __restrict__ bias, const void* __restrict__ resv,
            __half* __restrict__ kh, __half* __restrict__ vh) {
    constexpr int MWARPS = (BN == 128) ? 2 : 4;
    constexpr int MT     = (BN == 128) ? 4 : 2;
    constexpr int CB     = BN / 8;
    constexpr int ASTB_  = 16384;
    constexpr int BSTB_  = 64 * BN * 2;
    constexpr int STGB_  = ASTB_ + BSTB_;

    extern __shared__ char smc[];
    uint32_t sb = smem_u32(smc);
    const int tid  = threadIdx.x;
    const int lane = tid & 31;
    const int w    = tid >> 5;
    const int wm   = w % MWARPS;
    const int wn   = w / MWARPS;
    const int g    = lane >> 2;
    const int qt   = lane & 3;
    const int sub  = lane >> 3;
    const int rin  = lane & 7;

    const __half* Ab = A + (size_t)blockIdx.y * 128 * K;
    const __half* Bb = B + (size_t)blockIdx.x * BN;
    const int S = K >> 6;

    auto load = [&](int s, int buf) {
        uint32_t ab  = sb + buf * STGB_;
        uint32_t bbs = ab + ASTB_;
        const __half* Ac = Ab + (s << 6);
        const __half* Bc = Bb + (size_t)(s << 6) * Nc;
        #pragma unroll
        for (int r2 = 0; r2 < 4; r2++) {
            int idx = tid + (r2 << 8);
            int row = idx >> 3, q = idx & 7;
            cp_async16(ab + aoff(row, q), Ac + (size_t)row * K + (q << 3));
        }
        #pragma unroll
        for (int r2 = 0; r2 < BN / 32; r2++) {
            int idx = tid + (r2 << 8);
            int k = idx / CB, c = idx % CB;
            cp_async16(bbs + boff<CB>(k, c), Bc + (size_t)k * Nc + (c << 3));
        }
        cp_commit();
    };

    float acc[MT][4][4];
    #pragma unroll
    for (int i = 0; i < MT; i++)
        #pragma unroll
        for (int j = 0; j < 4; j++)
            #pragma unroll
            for (int q = 0; q < 4; q++) acc[i][j][q] = 0.f;

    load(0, 0);
    load(1, 1);

    for (int s = 0; s < S; s++) {
        int buf = s % 3;
        if (s + 1 < S) cp_wait<1>(); else cp_wait<0>();
        __syncthreads();
        if (s + 2 < S) load(s + 2, (s + 2) % 3);

        uint32_t ab  = sb + buf * STGB_;
        uint32_t bbs = ab + ASTB_;
        #pragma unroll
        for (int ks = 0; ks < 4; ks++) {
            uint32_t af[MT][4];
            #pragma unroll
            for (int mt = 0; mt < MT; mt++) {
                int m = wm * (MT * 16) + mt * 16 + (sub & 1) * 8 + rin;
                int q = ks * 2 + (sub >> 1);
                ldsm4(af[mt], ab + aoff(m, q));
            }
            uint32_t bf[2][4];
            #pragma unroll
            for (int p = 0; p < 2; p++) {
                int k = ks * 16 + (sub & 1) * 8 + rin;
                int c = wn * 4 + p * 2 + (sub >> 1);
                ldsm4t(bf[p], bbs + boff<CB>(k, c));
            }
            #pragma unroll
            for (int mt = 0; mt < MT; mt++)
                #pragma unroll
                for (int nt = 0; nt < 4; nt++)
                    mma_f16(acc[mt][nt], af[mt], &bf[nt >> 1][(nt & 1) * 2]);
        }
        __syncthreads();
    }

    #pragma unroll
    for (int mt = 0; mt < MT; mt++) {
        int row0 = blockIdx.y * 128 + wm * (MT * 16) + mt * 16 + g;
        #pragma unroll
        for (int nt = 0; nt < 4; nt++) {
            int col = blockIdx.x * BN + wn * 32 + nt * 8 + qt * 2;
            #pragma unroll
            for (int h = 0; h < 2; h++) {
                int row = row0 + h * 8;
                float v0 = acc[mt][nt][h * 2 + 0];
                float v1 = acc[mt][nt][h * 2 + 1];
                if (EPI == 2) {
                    v0 += bias[col];
                    v1 += bias[col + 1];
                    v0 = 0.5f * v0 * (1.0f + erff(v0 * 0.70710678118654752f));
                    v1 = 0.5f * v1 * (1.0f + erff(v1 * 0.70710678118654752f));
                    *(__half2*)((__half*)Cv + (size_t)row * Nc + col) = __floats2half2_rn(v0, v1);
                } else if (EPI == 3) {
                    if (col < CC) {
                        *(__half2*)((__half*)Cv + (size_t)row * CC + col) = __floats2half2_rn(v0, v1);
                    } else if (col < 2 * CC) {
                        *(__half2*)(kh + (size_t)row * CC + (col - CC)) =
                            __floats2half2_rn(expf(v0), expf(v1));
                    } else {
                        *(__half2*)(vh + (size_t)row * CC + (col - 2 * CC)) = __floats2half2_rn(v0, v1);
                    }
                } else {
                    float2 r2 = __half22float2(*(const __half2*)((const __half*)resv + (size_t)row * Nc + col));
                    v0 += bias[col]     + r2.x;
                    v1 += bias[col + 1] + r2.y;
                    if (EPI == 4) {
                        *(__half2*)((__half*)Cv + (size_t)row * Nc + col) = __floats2half2_rn(v0, v1);
                    } else {
                        *(float2*)((float*)Cv + (size_t)row * Nc + col) = make_float2(v0, v1);
                    }
                }
            }
        }
    }
}

// ---------------- kv partials ----------------
__global__ __launch_bounds__(256)
void kv_build_kernel(int b0) {
    int seg = blockIdx.x;
    int b   = b0 + blockIdx.y;
    int t   = threadIdx.x;
    int head = t >> 5, i = t & 31;

    __shared__ __align__(16) float ksf[16][256];
    __shared__ __align__(16) float vsf[16][256];

    float acc[32];
    #pragma unroll
    for (int j = 0; j < 32; j++) acc[j] = 0.f;
    float ssum = 0.f;

    const __half* kb = g_kh + ((size_t)b * NN + seg * 32) * CC;
    const __half* vb = g_vh + ((size_t)b * NN + seg * 32) * CC;

    for (int tile = 0; tile < 2; tile++) {
        #pragma unroll
        for (int r2 = 0; r2 < 2; r2++) {
            int idx = t + (r2 << 8);
            int row = idx >> 5, c8 = (idx & 31) << 3;
            size_t goff = (size_t)(tile * 16 + row) * CC + c8;
            uint4 kv4 = *(const uint4*)(kb + goff);
            uint4 vv4 = *(const uint4*)(vb + goff);
            const __half2* kp = (const __half2*)&kv4;
            const __half2* vp = (const __half2*)&vv4;
            #pragma unroll
            for (int p = 0; p < 4; p++) {
                float2 kf = __half22float2(kp[p]);
                float2 vf = __half22float2(vp[p]);
                ksf[row][c8 + p * 2]     = kf.x;
                ksf[row][c8 + p * 2 + 1] = kf.y;
                vsf[row][c8 + p * 2]     = vf.x;
                vsf[row][c8 + p * 2 + 1] = vf.y;
            }
        }
        __syncthreads();
        #pragma unroll
        for (int nn = 0; nn < 16; nn++) {
            float e = ksf[nn][head * CH + i];
            ssum += e;
            const float* vrow = &vsf[nn][head * CH];
            #pragma unroll
            for (int j4 = 0; j4 < 8; j4++) {
                float4 v4 = *(const float4*)(vrow + j4 * 4);
                acc[j4 * 4 + 0] += e * v4.x;
                acc[j4 * 4 + 1] += e * v4.y;
                acc[j4 * 4 + 2] += e * v4.z;
                acc[j4 * 4 + 3] += e * v4.w;
            }
        }
        __syncthreads();
    }

    int bh = b * NHEAD + head;
    float* kvp = g_kvp + ((size_t)(seg * 64 + bh) * CH + i) * CH;
    #pragma unroll
    for (int j4 = 0; j4 < 8; j4++)
        *(float4*)(kvp + j4 * 4) = make_float4(acc[j4*4], acc[j4*4+1], acc[j4*4+2], acc[j4*4+3]);
    g_ksp[(seg * 64 + bh) * CH + i] = ssum;
}

// ---------------- kv reduce+normalize + domain gating, per quarter ----------------
__global__ void kv_norm_da_kernel(const float* __restrict__ dl,
                                  const float* __restrict__ w1, const float* __restrict__ b1,
                                  const float* __restrict__ w2, const float* __restrict__ b2,
                                  int b0, int nb) {
    int nbh = nb * NHEAD;
    if ((int)blockIdx.x < nbh) {
        int bh = b0 * NHEAD + blockIdx.x;
        int t = threadIdx.x;
        int i = t >> 5, j = t & 31;
        float s = 0.f, kvv = 0.f;
        for (int p = 0; p < KSEG; p++) {
            s   += g_ksp[(p * 64 + bh) * CH + i];
            kvv += g_kvp[((size_t)(p * 64 + bh) * CH + i) * CH + j];
        }
        g_kv[((size_t)bh * CH + i) * CH + j] = kvv / s;
        return;
    }
    int t = threadIdx.x;
    if (t >= 256) return;
    __shared__ float hid[128];
    __shared__ float outb[4 * CC];
    for (int bi = 0; bi < nb; bi++) {
        int b = b0 + bi;
        if (t < 128) {
            float a = b1[t];
            #pragma unroll
            for (int k = 0; k < 4; k++) a += dl[b * 4 + k] * w1[k * 128 + t];
            hid[t] = fmaxf(a, 0.f);
        }
        asm volatile("bar.sync 1, 256;" ::: "memory");
        float o = b2[t];
        for (int i = 0; i < 128; i++) o += hid[i] * w2[i * CC + t];
        outb[bi * CC + t] = o;
        asm volatile("bar.sync 1, 256;" ::: "memory");
    }
    if (t < nb * 32) {
        int bb = t >> 5;
        int ch = t & 31;
        float m = -1e30f;
        #pragma unroll
        for (int hd = 0; hd < NHEAD; hd++)
            m = fmaxf(m, outb[bb * CC + hd * CH + ch]);
        float e[NHEAD], s = 0.f;
        #pragma unroll
        for (int hd = 0; hd < NHEAD; hd++) {
            e[hd] = expf(outb[bb * CC + hd * CH + ch] - m);
            s += e[hd];
        }
        float inv = 1.0f / s;
        #pragma unroll
        for (int hd = 0; hd < NHEAD; hd++)
            g_da[(b0 + bb) * CC + hd * CH + ch] = e[hd] * inv;
    }
}

// ---------------- conv-RPE inner ----------------
template<int KSZ>
__device__ __forceinline__ void conv8(float* cv0, float* cv1,
                                      const __half* vb, const float* wb0, const float* wb1,
                                      int hh, int ww0) {
    constexpr int RAD = KSZ / 2;
    #pragma unroll
    for (int dy = 0; dy < KSZ; dy++) {
        int y = hh - RAD + dy;
        if ((unsigned)y >= HH) continue;
        float w0r[KSZ], w1r[KSZ];
        #pragma unroll
        for (int j = 0; j < KSZ; j++) {
            w0r[j] = wb0[dy * KSZ + j];
            w1r[j] = wb1[dy * KSZ + j];
        }
        const __half* vrow = vb + (size_t)(y * WW) * CC;
        #pragma unroll
        for (int xx = 0; xx < 8 + 2 * RAD; xx++) {
            int gx = ww0 - RAD + xx;
            if ((unsigned)gx >= WW) continue;
            float2 vf = __half22float2(*(const __half2*)(vrow + (size_t)gx * CC));
            #pragma unroll
            for (int tok = 0; tok < 8; tok++) {
                int j = xx - tok;
                if (j < 0 || j >= KSZ) continue;
                cv0[tok] += vf.x * w0r[j];
                cv1[tok] += vf.y * w1r[j];
            }
        }
    }
}

// ---------------- factor-att + conv-RPE + gating, 8 tokens per block ----------------
__global__ __launch_bounds__(128)
void attn_build_kernel(const float* __restrict__ w3, const float* __restrict__ b3,
                       const float* __restrict__ w5, const float* __restrict__ b5,
                       const float* __restrict__ w7, const float* __restrict__ b7,
                       int b0) {
    int blk = blockIdx.x;
    int b   = b0 + blk / (NN / 8);
    int rem = blk % (NN / 8);
    int hh  = rem / (WW / 8);
    int ww0 = (rem % (WW / 8)) * 8;
    int t   = threadIdx.x;
    int c0  = t * 2;
    int head = c0 >> 5;
    int ch0  = c0 & 31;

    __shared__ float qs[8][CC];
    size_t row0 = (size_t)b * NN + hh * WW + ww0;
    #pragma unroll
    for (int tok = 0; tok < 8; tok++) {
        float2 qv = __half22float2(*(const __half2*)(g_qh + (row0 + tok) * CC + c0));
        *(float2*)&qs[tok][c0] = qv;
    }
    __syncthreads();

    float fa0[8], fa1[8];
    #pragma unroll
    for (int tok = 0; tok < 8; tok++) { fa0[tok] = 0.f; fa1[tok] = 0.f; }
    const float* kvb = g_kv + (size_t)(b * NHEAD + head) * CH * CH;
    #pragma unroll
    for (int k2 = 0; k2 < CH; k2++) {
        float2 kv2 = *(const float2*)(kvb + k2 * CH + ch0);
        #pragma unroll
        for (int tok = 0; tok < 8; tok++) {
            float qv = qs[tok][head * CH + k2];
            fa0[tok] += qv * kv2.x;
            fa1[tok] += qv * kv2.y;
        }
    }

    float cv0[8], cv1[8];
    const __half* vb = g_vh + (size_t)b * NN * CC + c0;
    if (c0 < 64) {
        #pragma unroll
        for (int tok = 0; tok < 8; tok++) { cv0[tok] = b3[c0]; cv1[tok] = b3[c0 + 1]; }
        conv8<3>(cv0, cv1, vb, w3 + c0 * 9, w3 + (c0 + 1) * 9, hh, ww0);
    } else if (c0 < 160) {
        #pragma unroll
        for (int tok = 0; tok < 8; tok++) { cv0[tok] = b5[c0 - 64]; cv1[tok] = b5[c0 - 63]; }
        conv8<5>(cv0, cv1, vb, w5 + (c0 - 64) * 25, w5 + (c0 - 63) * 25, hh, ww0);
    } else {
        #pragma unroll
        for (int tok = 0; tok < 8; tok++) { cv0[tok] = b7[c0 - 160]; cv1[tok] = b7[c0 - 159]; }
        conv8<7>(cv0, cv1, vb, w7 + (c0 - 160) * 49, w7 + (c0 - 159) * 49, hh, ww0);
    }

    float2 da2 = *(const float2*)(g_da + b * CC + c0);
    const float scale = 0.17677669529663687f;
    #pragma unroll
    for (int tok = 0; tok < 8; tok++) {
        float q0 = qs[tok][c0], q1 = qs[tok][c0 + 1];
        float o0 = da2.x * (fa0[tok] * scale + q0 * cv0[tok]);
        float o1 = da2.y * (fa1[tok] * scale + q1 * cv1[tok]);
        *(__half2*)(g_atth + (row0 + tok) * CC + c0) = __floats2half2_rn(o0, o1);
    }
}

// ---------------- launch ----------------
extern "C" void kernel_launch(void* const* d_in, const int* in_sizes, int n_in,
                              void* d_out, int out_size) {
    const float* x      = (const float*)d_in[0];
    const float* dl     = (const float*)d_in[1];
    const float* cpe_w  = (const float*)d_in[2];
    const float* cpe_b  = (const float*)d_in[3];
    const float* ln1_g  = (const float*)d_in[4];
    const float* ln1_b  = (const float*)d_in[5];
    const float* qkv_w  = (const float*)d_in[6];
    const float* proj_w = (const float*)d_in[7];
    const float* proj_b = (const float*)d_in[8];
    const float* dl_w1  = (const float*)d_in[9];
    const float* dl_b1  = (const float*)d_in[10];
    const float* dl_w2  = (const float*)d_in[11];
    const float* dl_b2  = (const float*)d_in[12];
    const float* w3     = (const float*)d_in[13];
    const float* b3     = (const float*)d_in[14];
    const float* w5     = (const float*)d_in[15];
    const float* b5     = (const float*)d_in[16];
    const float* w7     = (const float*)d_in[17];
    const float* b7     = (const float*)d_in[18];
    const float* ln2_g  = (const float*)d_in[19];
    const float* ln2_b  = (const float*)d_in[20];
    const float* fc1_w  = (const float*)d_in[21];
    const float* fc1_b  = (const float*)d_in[22];
    const float* fc2_w  = (const float*)d_in[23];
    const float* fc2_b  = (const float*)d_in[24];
    float* out = (float*)d_out;

    __half *p_x1h, *p_x2h, *p_qh, *p_kh, *p_vh, *p_curh, *p_atth, *p_hidh, *p_wth;
    cudaGetSymbolAddress((void**)&p_x1h,  g_x1h);
    cudaGetSymbolAddress((void**)&p_x2h,  g_x2h);
    cudaGetSymbolAddress((void**)&p_qh,   g_qh);
    cudaGetSymbolAddress((void**)&p_kh,   g_kh);
    cudaGetSymbolAddress((void**)&p_vh,   g_vh);
    cudaGetSymbolAddress((void**)&p_curh, g_curh);
    cudaGetSymbolAddress((void**)&p_atth, g_atth);
    cudaGetSymbolAddress((void**)&p_hidh, g_hidh);
    cudaGetSymbolAddress((void**)&p_wth,  g_wth);

    __half* qkvH  = p_wth;
    __half* projH = p_wth + 196608;
    __half* fc1H  = p_wth + 262144;
    __half* fc2H  = p_wth + 524288;

    const int GSM128 = 3 * (16384 + 16384);
    const int GSM64  = 3 * (16384 + 8192);
    cudaFuncSetAttribute((gemm_h<3,128>), cudaFuncAttributeMaxDynamicSharedMemorySize, GSM128);
    cudaFuncSetAttribute((gemm_h<2,128>), cudaFuncAttributeMaxDynamicSharedMemorySize, GSM128);
    cudaFuncSetAttribute((gemm_h<4,64>),  cudaFuncAttributeMaxDynamicSharedMemorySize, GSM64);
    cudaFuncSetAttribute((gemm_h<5,64>),  cudaFuncAttributeMaxDynamicSharedMemorySize, GSM64);

    static cudaStream_t sS[3] = {nullptr, nullptr, nullptr};
    static cudaEvent_t  evFork = nullptr, evWq = nullptr, evWr = nullptr;
    static cudaEvent_t  evJ[3] = {nullptr, nullptr, nullptr};
    if (sS[0] == nullptr) {
        for (int i = 0; i < 3; i++) {
            cudaStreamCreateWithFlags(&sS[i], cudaStreamNonBlocking);
            cudaEventCreateWithFlags(&evJ[i], cudaEventDisableTiming);
        }
        cudaEventCreateWithFlags(&evFork, cudaEventDisableTiming);
        cudaEventCreateWithFlags(&evWq, cudaEventDisableTiming);
        cudaEventCreateWithFlags(&evWr, cudaEventDisableTiming);
    }

    const int QB  = 2;
    const int QBN = QB * NN;

    // fork side streams from stream 0 FIRST
    cudaEventRecord(evFork, 0);
    for (int i = 0; i < 3; i++) cudaStreamWaitEvent(sS[i], evFork, 0);

    // weight conversion first on stream 0
    f2h_one<<<192, 256, 0, 0>>>(qkv_w, qkvH);
    cudaEventRecord(evWq, 0);
    f2h_rest<<<576, 256, 0, 0>>>(proj_w, fc1_w, fc2_w, p_wth);
    cudaEventRecord(evWr, 0);

    // cpe_ln1 for all quarters (overlaps with weight conversion)
    cpe_ln1_kernel<<<QBN / 8, 128, 0, 0>>>(x, cpe_w, cpe_b, ln1_g, ln1_b, 0);
    cpe_ln1_kernel<<<QBN / 8, 128, 0, sS[0]>>>(x, cpe_w, cpe_b, ln1_g, ln1_b, (2 * NN) / 8);
    cpe_ln1_kernel<<<QBN / 8, 128, 0, sS[1]>>>(x, cpe_w, cpe_b, ln1_g, ln1_b, (4 * NN) / 8);
    cpe_ln1_kernel<<<QBN / 8, 128, 0, sS[2]>>>(x, cpe_w, cpe_b, ln1_g, ln1_b, (6 * NN) / 8);

    auto rest = [&](cudaStream_t st, int b0, bool side) {
        size_t off = (size_t)b0 * NN;
        if (side) cudaStreamWaitEvent(st, evWq, 0);
        gemm_h<3,128><<<dim3(QKVW/128, QBN/128), 256, GSM128, st>>>(
            p_curh + off * CC, qkvH, p_qh + off * CC, QBN, QKVW, CC,
            nullptr, nullptr, p_kh + off * CC, p_vh + off * CC);
        kv_build_kernel<<<dim3(KSEG, QB), 256, 0, st>>>(b0);
        kv_norm_da_kernel<<<QB * NHEAD + 1, 1024, 0, st>>>(dl, dl_w1, dl_b1, dl_w2, dl_b2, b0, QB);
        attn_build_kernel<<<QB * NN / 8, 128, 0, st>>>(w3, b3, w5, b5, w7, b7, b0);
        if (side) cudaStreamWaitEvent(st, evWr, 0);
        gemm_h<4,64><<<dim3(CC/64, QBN/128), 256, GSM64, st>>>(
            p_atth + off * CC, projH, p_x2h + off * CC, QBN, CC, CC,
            proj_b, p_x1h + off * CC, nullptr, nullptr);
        ln2_kernel<<<QBN / 2, 256, 0, st>>>(ln2_g, ln2_b, (int)off);
        gemm_h<2,128><<<dim3(MH/128, QBN/128), 256, GSM128, st>>>(
            p_curh + off * CC, fc1H, p_hidh + off * MH, QBN, MH, CC,
            fc1_b, nullptr, nullptr, nullptr);
        gemm_h<5,64><<<dim3(CC/64, QBN/128), 256, GSM64, st>>>(
            p_hidh + off * MH, fc2H, out + off * CC, QBN, CC, MH,
            fc2_b, p_x2h + off * CC, nullptr, nullptr);
    };

    rest((cudaStream_t)0, 0, false);
    rest(sS[0], 2, true);
    rest(sS[1], 4, true);
    rest(sS[2], 6, true);

    for (int i = 0; i < 3; i++) {
        cudaEventRecord(evJ[i], sS[i]);
        cudaStreamWaitEvent((cudaStream_t)0, evJ[i], 0);
    }
}

// round 15
// speedup vs baseline: 1.0101x; 1.0101x over previous
#include <cuda_runtime.h>
#include <cuda_fp16.h>
#include <stdint.h>
#include <math.h>

// ---------------- static problem shapes ----------------
#define BB    8
#define HH    56
#define WW    56
#define NN    (HH*WW)        // 3136
#define CC    256
#define NHEAD 8
#define CH    32
#define BN_TOT (BB*NN)       // 25088
#define QKVW  768
#define MH    1024
#define KSEG  98             // 32-token segments

// ---------------- scratch ----------------
__device__ __align__(16) __half g_x1h [BN_TOT*CC];
__device__ __align__(16) __half g_x2h [BN_TOT*CC];
__device__ __align__(16) __half g_qh  [BN_TOT*CC];
__device__ __align__(16) __half g_kh  [BN_TOT*CC];   // holds exp(k)
__device__ __align__(16) __half g_vh  [BN_TOT*CC];
__device__ __align__(16) __half g_curh[BN_TOT*CC];
__device__ __align__(16) __half g_atth[BN_TOT*CC];
__device__ __align__(16) __half g_hidh[BN_TOT*MH];
__device__ __align__(16) __half g_wth [786432];
__device__ float  g_kv  [64*CH*CH];
__device__ float  g_da  [BB*CC];
__device__ float  g_kvp [KSEG*64*CH*CH];
__device__ float  g_ksp [KSEG*64*CH];

// ---------------- helpers ----------------
__device__ __forceinline__ uint32_t smem_u32(const void* p){
    uint32_t a; asm("{.reg .u64 t; cvta.to.shared.u64 t, %1; cvt.u32.u64 %0, t;}":"=r"(a):"l"(p)); return a;
}
__device__ __forceinline__ void cp_async16(uint32_t dst, const void* src){
    asm volatile("cp.async.cg.shared.global [%0], [%1], 16;"::"r"(dst),"l"(src):"memory");
}
__device__ __forceinline__ void cp_commit(){ asm volatile("cp.async.commit_group;":::"memory"); }
template<int N> __device__ __forceinline__ void cp_wait(){ asm volatile("cp.async.wait_group %0;"::"n"(N):"memory"); }

__device__ __forceinline__ void ldsm4(uint32_t* r, uint32_t addr){
    asm volatile("ldmatrix.sync.aligned.m8n8.x4.shared.b16 {%0,%1,%2,%3}, [%4];"
        :"=r"(r[0]),"=r"(r[1]),"=r"(r[2]),"=r"(r[3]):"r"(addr));
}
__device__ __forceinline__ void ldsm4t(uint32_t* r, uint32_t addr){
    asm volatile("ldmatrix.sync.aligned.m8n8.x4.trans.shared.b16 {%0,%1,%2,%3}, [%4];"
        :"=r"(r[0]),"=r"(r[1]),"=r"(r[2]),"=r"(r[3]):"r"(addr));
}
__device__ __forceinline__ void mma_f16(float* d, const uint32_t* a, const uint32_t* b){
    asm volatile(
        "mma.sync.aligned.m16n8k16.row.col.f32.f16.f16.f32 "
        "{%0,%1,%2,%3}, {%4,%5,%6,%7}, {%8,%9}, {%0,%1,%2,%3};"
        : "+f"(d[0]),"+f"(d[1]),"+f"(d[2]),"+f"(d[3])
        : "r"(a[0]),"r"(a[1]),"r"(a[2]),"r"(a[3]),"r"(b[0]),"r"(b[1]));
}

__device__ __forceinline__ uint32_t aoff(int r, int q){
    return (uint32_t)((r << 7) + (((q ^ (r & 7)) & 7) << 4));
}
template<int CB>
__device__ __forceinline__ uint32_t boff(int k, int c){
    if (CB == 16) return (uint32_t)((k << 8) + ((((c & 8) | ((c & 7) ^ (k & 7)))) << 4));
    else          return (uint32_t)((k << 7) + ((((c ^ (k & 7)) & 7)) << 4));
}

// ---------------- all-weights fp32 -> half ----------------
__global__ void f2h_all(const float* __restrict__ a, const float* __restrict__ b,
                        const float* __restrict__ c, const float* __restrict__ d,
                        __half* __restrict__ dst){
    int i = (blockIdx.x * blockDim.x + threadIdx.x) * 4;
    const float* src; int off;
    if      (i < 196608) { src = a; off = 0; }
    else if (i < 262144) { src = b; off = 196608; }
    else if (i < 524288) { src = c; off = 262144; }
    else                 { src = d; off = 524288; }
    float4 v = *(const float4*)(src + (i - off));
    __half2 h0 = __floats2half2_rn(v.x, v.y);
    __half2 h1 = __floats2half2_rn(v.z, v.w);
    *(uint2*)(dst + i) = make_uint2(*(uint32_t*)&h0, *(uint32_t*)&h1);
}

// ---------------- CPE dw3x3 + residual + LN1, 8-token tiles ----------------
__global__ __launch_bounds__(128)
void cpe_ln1_kernel(const float* __restrict__ x,
                    const float* __restrict__ cpe_w,
                    const float* __restrict__ cpe_b,
                    const float* __restrict__ ln_g,
                    const float* __restrict__ ln_b, int blk0) {
    int blk = blk0 + blockIdx.x;
    int b   = blk / (NN / 8);
    int rem = blk % (NN / 8);
    int hh  = rem / (WW / 8);
    int ww0 = (rem % (WW / 8)) * 8;
    int t   = threadIdx.x;
    int c0  = t * 2;

    const float* xb = x + (size_t)b * NN * CC + c0;
    const float* w0 = cpe_w + c0 * 9;
    const float* w1 = w0 + 9;
    float w0r[9], w1r[9];
    #pragma unroll
    for (int j = 0; j < 9; j++) { w0r[j] = w0[j]; w1r[j] = w1[j]; }

    float cv0[8], cv1[8];
    float bias0 = cpe_b[c0], bias1 = cpe_b[c0 + 1];
    #pragma unroll
    for (int tok = 0; tok < 8; tok++) { cv0[tok] = bias0; cv1[tok] = bias1; }
    float xc0[8], xc1[8];

    #pragma unroll
    for (int dy = 0; dy < 3; dy++) {
        int y = hh - 1 + dy;
        bool yok = (unsigned)y < HH;
        #pragma unroll
        for (int xx = 0; xx < 10; xx++) {
            int gx = ww0 - 1 + xx;
            float2 xv = make_float2(0.f, 0.f);
            if (yok && (unsigned)gx < WW)
                xv = *(const float2*)(xb + (size_t)(y * WW + gx) * CC);
            if (dy == 1 && xx >= 1 && xx <= 8) { xc0[xx - 1] = xv.x; xc1[xx - 1] = xv.y; }
            #pragma unroll
            for (int tok = 0; tok < 8; tok++) {
                int j = xx - tok;
                if (j < 0 || j >= 3) continue;
                cv0[tok] += xv.x * w0r[dy * 3 + j];
                cv1[tok] += xv.y * w1r[dy * 3 + j];
            }
        }
    }

    size_t row0 = (size_t)b * NN + hh * WW + ww0;
    __shared__ float s1[128][9];
    __shared__ float s2[128][9];
    #pragma unroll
    for (int tok = 0; tok < 8; tok++) {
        cv0[tok] += xc0[tok];
        cv1[tok] += xc1[tok];
        *(__half2*)(g_x1h + (row0 + tok) * CC + c0) = __floats2half2_rn(cv0[tok], cv1[tok]);
        s1[t][tok] = cv0[tok] + cv1[tok];
        s2[t][tok] = cv0[tok] * cv0[tok] + cv1[tok] * cv1[tok];
    }
    __syncthreads();
    for (int off = 64; off > 0; off >>= 1) {
        if (t < off) {
            #pragma unroll
            for (int tok = 0; tok < 8; tok++) {
                s1[t][tok] += s1[t + off][tok];
                s2[t][tok] += s2[t + off][tok];
            }
        }
        __syncthreads();
    }
    float g0 = ln_g[c0], g1 = ln_g[c0 + 1];
    float bb0 = ln_b[c0], bb1 = ln_b[c0 + 1];
    #pragma unroll
    for (int tok = 0; tok < 8; tok++) {
        float mean = s1[0][tok] * (1.0f / CC);
        float var  = s2[0][tok] * (1.0f / CC) - mean * mean;
        float inv  = rsqrtf(var + 1e-5f);
        float o0 = (cv0[tok] - mean) * inv * g0 + bb0;
        float o1 = (cv1[tok] - mean) * inv * g1 + bb1;
        *(__half2*)(g_curh + (row0 + tok) * CC + c0) = __floats2half2_rn(o0, o1);
    }
}

// ---------------- LN2 (reads half x2) ----------------
__global__ void ln2_kernel(const float* __restrict__ ln_g,
                           const float* __restrict__ ln_b, int bn0) {
    int bn = bn0 + blockIdx.x;
    int t  = threadIdx.x;
    int c0 = t * 2;
    float2 xv = __half22float2(*(const __half2*)(g_x2h + (size_t)bn * CC + c0));
    __shared__ float s1[128];
    __shared__ float s2[128];
    s1[t] = xv.x + xv.y;
    s2[t] = xv.x * xv.x + xv.y * xv.y;
    __syncthreads();
    for (int off = 64; off > 0; off >>= 1) {
        if (t < off) { s1[t] += s1[t + off]; s2[t] += s2[t + off]; }
        __syncthreads();
    }
    float mean = s1[0] * (1.0f / CC);
    float var  = s2[0] * (1.0f / CC) - mean * mean;
    float inv  = rsqrtf(var + 1e-5f);
    float o0 = (xv.x - mean) * inv * ln_g[c0]     + ln_b[c0];
    float o1 = (xv.y - mean) * inv * ln_g[c0 + 1] + ln_b[c0 + 1];
    *(__half2*)(g_curh + (size_t)bn * CC + c0) = __floats2half2_rn(o0, o1);
}

// ---------------- fp16 tensor-core GEMM ----------------
// EPI 2: half C = gelu(acc+bias)
// EPI 3: qkv split all-half -> q, exp(k), v
// EPI 4: half C = acc + bias + half-res          (proj -> x2h)
// EPI 5: fp32 C = acc + bias + half-res          (fc2 -> out)
template <int EPI, int BN>
__global__ __launch_bounds__(256)
void gemm_h(const __half* __restrict__ A, const __half* __restrict__ B,
            void* __restrict__ Cv, int M, int Nc, int K,
            const float* __restrict__ bias, const void* __restrict__ resv,
            __half* __restrict__ kh, __half* __restrict__ vh) {
    constexpr int MWARPS = (BN == 128) ? 2 : 4;
    constexpr int MT     = (BN == 128) ? 4 : 2;
    constexpr int CB     = BN / 8;
    constexpr int ASTB_  = 16384;
    constexpr int BSTB_  = 64 * BN * 2;
    constexpr int STGB_  = ASTB_ + BSTB_;

    extern __shared__ char smc[];
    uint32_t sb = smem_u32(smc);
    const int tid  = threadIdx.x;
    const int lane = tid & 31;
    const int w    = tid >> 5;
    const int wm   = w % MWARPS;
    const int wn   = w / MWARPS;
    const int g    = lane >> 2;
    const int qt   = lane & 3;
    const int sub  = lane >> 3;
    const int rin  = lane & 7;

    const __half* Ab = A + (size_t)blockIdx.y * 128 * K;
    const __half* Bb = B + (size_t)blockIdx.x * BN;
    const int S = K >> 6;

    auto load = [&](int s, int buf) {
        uint32_t ab  = sb + buf * STGB_;
        uint32_t bbs = ab + ASTB_;
        const __half* Ac = Ab + (s << 6);
        const __half* Bc = Bb + (size_t)(s << 6) * Nc;
        #pragma unroll
        for (int r2 = 0; r2 < 4; r2++) {
            int idx = tid + (r2 << 8);
            int row = idx >> 3, q = idx & 7;
            cp_async16(ab + aoff(row, q), Ac + (size_t)row * K + (q << 3));
        }
        #pragma unroll
        for (int r2 = 0; r2 < BN / 32; r2++) {
            int idx = tid + (r2 << 8);
            int k = idx / CB, c = idx % CB;
            cp_async16(bbs + boff<CB>(k, c), Bc + (size_t)k * Nc + (c << 3));
        }
        cp_commit();
    };

    float acc[MT][4][4];
    #pragma unroll
    for (int i = 0; i < MT; i++)
        #pragma unroll
        for (int j = 0; j < 4; j++)
            #pragma unroll
            for (int q = 0; q < 4; q++) acc[i][j][q] = 0.f;

    load(0, 0);
    load(1, 1);

    for (int s = 0; s < S; s++) {
        int buf = s % 3;
        if (s + 1 < S) cp_wait<1>(); else cp_wait<0>();
        __syncthreads();
        if (s + 2 < S) load(s + 2, (s + 2) % 3);

        uint32_t ab  = sb + buf * STGB_;
        uint32_t bbs = ab + ASTB_;
        #pragma unroll
        for (int ks = 0; ks < 4; ks++) {
            uint32_t af[MT][4];
            #pragma unroll
            for (int mt = 0; mt < MT; mt++) {
                int m = wm * (MT * 16) + mt * 16 + (sub & 1) * 8 + rin;
                int q = ks * 2 + (sub >> 1);
                ldsm4(af[mt], ab + aoff(m, q));
            }
            uint32_t bf[2][4];
            #pragma unroll
            for (int p = 0; p < 2; p++) {
                int k = ks * 16 + (sub & 1) * 8 + rin;
                int c = wn * 4 + p * 2 + (sub >> 1);
                ldsm4t(bf[p], bbs + boff<CB>(k, c));
            }
            #pragma unroll
            for (int mt = 0; mt < MT; mt++)
                #pragma unroll
                for (int nt = 0; nt < 4; nt++)
                    mma_f16(acc[mt][nt], af[mt], &bf[nt >> 1][(nt & 1) * 2]);
        }
        __syncthreads();
    }

    #pragma unroll
    for (int mt = 0; mt < MT; mt++) {
        int row0 = blockIdx.y * 128 + wm * (MT * 16) + mt * 16 + g;
        #pragma unroll
        for (int nt = 0; nt < 4; nt++) {
            int col = blockIdx.x * BN + wn * 32 + nt * 8 + qt * 2;
            #pragma unroll
            for (int h = 0; h < 2; h++) {
                int row = row0 + h * 8;
                float v0 = acc[mt][nt][h * 2 + 0];
                float v1 = acc[mt][nt][h * 2 + 1];
                if (EPI == 2) {
                    v0 += bias[col];
                    v1 += bias[col + 1];
                    v0 = 0.5f * v0 * (1.0f + erff(v0 * 0.70710678118654752f));
                    v1 = 0.5f * v1 * (1.0f + erff(v1 * 0.70710678118654752f));
                    *(__half2*)((__half*)Cv + (size_t)row * Nc + col) = __floats2half2_rn(v0, v1);
                } else if (EPI == 3) {
                    if (col < CC) {
                        *(__half2*)((__half*)Cv + (size_t)row * CC + col) = __floats2half2_rn(v0, v1);
                    } else if (col < 2 * CC) {
                        *(__half2*)(kh + (size_t)row * CC + (col - CC)) =
                            __floats2half2_rn(expf(v0), expf(v1));
                    } else {
                        *(__half2*)(vh + (size_t)row * CC + (col - 2 * CC)) = __floats2half2_rn(v0, v1);
                    }
                } else {
                    float2 r2 = __half22float2(*(const __half2*)((const __half*)resv + (size_t)row * Nc + col));
                    v0 += bias[col]     + r2.x;
                    v1 += bias[col + 1] + r2.y;
                    if (EPI == 4) {
                        *(__half2*)((__half*)Cv + (size_t)row * Nc + col) = __floats2half2_rn(v0, v1);
                    } else {
                        *(float2*)((float*)Cv + (size_t)row * Nc + col) = make_float2(v0, v1);
                    }
                }
            }
        }
    }
}

// ---------------- kv partials ----------------
__global__ __launch_bounds__(256)
void kv_build_kernel(int b0) {
    int seg = blockIdx.x;
    int b   = b0 + blockIdx.y;
    int t   = threadIdx.x;
    int head = t >> 5, i = t & 31;

    __shared__ __align__(16) float ksf[16][256];
    __shared__ __align__(16) float vsf[16][256];

    float acc[32];
    #pragma unroll
    for (int j = 0; j < 32; j++) acc[j] = 0.f;
    float ssum = 0.f;

    const __half* kb = g_kh + ((size_t)b * NN + seg * 32) * CC;
    const __half* vb = g_vh + ((size_t)b * NN + seg * 32) * CC;

    for (int tile = 0; tile < 2; tile++) {
        #pragma unroll
        for (int r2 = 0; r2 < 2; r2++) {
            int idx = t + (r2 << 8);
            int row = idx >> 5, c8 = (idx & 31) << 3;
            size_t goff = (size_t)(tile * 16 + row) * CC + c8;
            uint4 kv4 = *(const uint4*)(kb + goff);
            uint4 vv4 = *(const uint4*)(vb + goff);
            const __half2* kp = (const __half2*)&kv4;
            const __half2* vp = (const __half2*)&vv4;
            #pragma unroll
            for (int p = 0; p < 4; p++) {
                float2 kf = __half22float2(kp[p]);
                float2 vf = __half22float2(vp[p]);
                ksf[row][c8 + p * 2]     = kf.x;
                ksf[row][c8 + p * 2 + 1] = kf.y;
                vsf[row][c8 + p * 2]     = vf.x;
                vsf[row][c8 + p * 2 + 1] = vf.y;
            }
        }
        __syncthreads();
        #pragma unroll
        for (int nn = 0; nn < 16; nn++) {
            float e = ksf[nn][head * CH + i];
            ssum += e;
            const float* vrow = &vsf[nn][head * CH];
            #pragma unroll
            for (int j4 = 0; j4 < 8; j4++) {
                float4 v4 = *(const float4*)(vrow + j4 * 4);
                acc[j4 * 4 + 0] += e * v4.x;
                acc[j4 * 4 + 1] += e * v4.y;
                acc[j4 * 4 + 2] += e * v4.z;
                acc[j4 * 4 + 3] += e * v4.w;
            }
        }
        __syncthreads();
    }

    int bh = b * NHEAD + head;
    float* kvp = g_kvp + ((size_t)(seg * 64 + bh) * CH + i) * CH;
    #pragma unroll
    for (int j4 = 0; j4 < 8; j4++)
        *(float4*)(kvp + j4 * 4) = make_float4(acc[j4*4], acc[j4*4+1], acc[j4*4+2], acc[j4*4+3]);
    g_ksp[(seg * 64 + bh) * CH + i] = ssum;
}

// ---------------- kv reduce+normalize + domain gating, per quarter ----------------
__global__ void kv_norm_da_kernel(const float* __restrict__ dl,
                                  const float* __restrict__ w1, const float* __restrict__ b1,
                                  const float* __restrict__ w2, const float* __restrict__ b2,
                                  int b0, int nb) {
    int nbh = nb * NHEAD;
    if ((int)blockIdx.x < nbh) {
        int bh = b0 * NHEAD + blockIdx.x;
        int t = threadIdx.x;
        int i = t >> 5, j = t & 31;
        float s = 0.f, kvv = 0.f;
        for (int p = 0; p < KSEG; p++) {
            s   += g_ksp[(p * 64 + bh) * CH + i];
            kvv += g_kvp[((size_t)(p * 64 + bh) * CH + i) * CH + j];
        }
        g_kv[((size_t)bh * CH + i) * CH + j] = kvv / s;
        return;
    }
    int t = threadIdx.x;
    if (t >= 256) return;
    __shared__ float hid[128];
    __shared__ float outb[4 * CC];
    for (int bi = 0; bi < nb; bi++) {
        int b = b0 + bi;
        if (t < 128) {
            float a = b1[t];
            #pragma unroll
            for (int k = 0; k < 4; k++) a += dl[b * 4 + k] * w1[k * 128 + t];
            hid[t] = fmaxf(a, 0.f);
        }
        asm volatile("bar.sync 1, 256;" ::: "memory");
        float o = b2[t];
        for (int i = 0; i < 128; i++) o += hid[i] * w2[i * CC + t];
        outb[bi * CC + t] = o;
        asm volatile("bar.sync 1, 256;" ::: "memory");
    }
    if (t < nb * 32) {
        int bb = t >> 5;
        int ch = t & 31;
        float m = -1e30f;
        #pragma unroll
        for (int hd = 0; hd < NHEAD; hd++)
            m = fmaxf(m, outb[bb * CC + hd * CH + ch]);
        float e[NHEAD], s = 0.f;
        #pragma unroll
        for (int hd = 0; hd < NHEAD; hd++) {
            e[hd] = expf(outb[bb * CC + hd * CH + ch] - m);
            s += e[hd];
        }
        float inv = 1.0f / s;
        #pragma unroll
        for (int hd = 0; hd < NHEAD; hd++)
            g_da[(b0 + bb) * CC + hd * CH + ch] = e[hd] * inv;
    }
}

// ---------------- conv-RPE inner ----------------
template<int KSZ>
__device__ __forceinline__ void conv8(float* cv0, float* cv1,
                                      const __half* vb, const float* wb0, const float* wb1,
                                      int hh, int ww0) {
    constexpr int RAD = KSZ / 2;
    #pragma unroll
    for (int dy = 0; dy < KSZ; dy++) {
        int y = hh - RAD + dy;
        if ((unsigned)y >= HH) continue;
        float w0r[KSZ], w1r[KSZ];
        #pragma unroll
        for (int j = 0; j < KSZ; j++) {
            w0r[j] = wb0[dy * KSZ + j];
            w1r[j] = wb1[dy * KSZ + j];
        }
        const __half* vrow = vb + (size_t)(y * WW) * CC;
        #pragma unroll
        for (int xx = 0; xx < 8 + 2 * RAD; xx++) {
            int gx = ww0 - RAD + xx;
            if ((unsigned)gx >= WW) continue;
            float2 vf = __half22float2(*(const __half2*)(vrow + (size_t)gx * CC));
            #pragma unroll
            for (int tok = 0; tok < 8; tok++) {
                int j = xx - tok;
                if (j < 0 || j >= KSZ) continue;
                cv0[tok] += vf.x * w0r[j];
                cv1[tok] += vf.y * w1r[j];
            }
        }
    }
}

// ---------------- factor-att + conv-RPE + gating, 8 tokens per block ----------------
__global__ __launch_bounds__(128)
void attn_build_kernel(const float* __restrict__ w3, const float* __restrict__ b3,
                       const float* __restrict__ w5, const float* __restrict__ b5,
                       const float* __restrict__ w7, const float* __restrict__ b7,
                       int b0) {
    int blk = blockIdx.x;
    int b   = b0 + blk / (NN / 8);
    int rem = blk % (NN / 8);
    int hh  = rem / (WW / 8);
    int ww0 = (rem % (WW / 8)) * 8;
    int t   = threadIdx.x;
    int c0  = t * 2;
    int head = c0 >> 5;
    int ch0  = c0 & 31;

    __shared__ float qs[8][CC];
    size_t row0 = (size_t)b * NN + hh * WW + ww0;
    #pragma unroll
    for (int tok = 0; tok < 8; tok++) {
        float2 qv = __half22float2(*(const __half2*)(g_qh + (row0 + tok) * CC + c0));
        *(float2*)&qs[tok][c0] = qv;
    }
    __syncthreads();

    float fa0[8], fa1[8];
    #pragma unroll
    for (int tok = 0; tok < 8; tok++) { fa0[tok] = 0.f; fa1[tok] = 0.f; }
    const float* kvb = g_kv + (size_t)(b * NHEAD + head) * CH * CH;
    #pragma unroll
    for (int k2 = 0; k2 < CH; k2++) {
        float2 kv2 = *(const float2*)(kvb + k2 * CH + ch0);
        #pragma unroll
        for (int tok = 0; tok < 8; tok++) {
            float qv = qs[tok][head * CH + k2];
            fa0[tok] += qv * kv2.x;
            fa1[tok] += qv * kv2.y;
        }
    }

    float cv0[8], cv1[8];
    const __half* vb = g_vh + (size_t)b * NN * CC + c0;
    if (c0 < 64) {
        #pragma unroll
        for (int tok = 0; tok < 8; tok++) { cv0[tok] = b3[c0]; cv1[tok] = b3[c0 + 1]; }
        conv8<3>(cv0, cv1, vb, w3 + c0 * 9, w3 + (c0 + 1) * 9, hh, ww0);
    } else if (c0 < 160) {
        #pragma unroll
        for (int tok = 0; tok < 8; tok++) { cv0[tok] = b5[c0 - 64]; cv1[tok] = b5[c0 - 63]; }
        conv8<5>(cv0, cv1, vb, w5 + (c0 - 64) * 25, w5 + (c0 - 63) * 25, hh, ww0);
    } else {
        #pragma unroll
        for (int tok = 0; tok < 8; tok++) { cv0[tok] = b7[c0 - 160]; cv1[tok] = b7[c0 - 159]; }
        conv8<7>(cv0, cv1, vb, w7 + (c0 - 160) * 49, w7 + (c0 - 159) * 49, hh, ww0);
    }

    float2 da2 = *(const float2*)(g_da + b * CC + c0);
    const float scale = 0.17677669529663687f;
    #pragma unroll
    for (int tok = 0; tok < 8; tok++) {
        float q0 = qs[tok][c0], q1 = qs[tok][c0 + 1];
        float o0 = da2.x * (fa0[tok] * scale + q0 * cv0[tok]);
        float o1 = da2.y * (fa1[tok] * scale + q1 * cv1[tok]);
        *(__half2*)(g_atth + (row0 + tok) * CC + c0) = __floats2half2_rn(o0, o1);
    }
}

// ---------------- launch ----------------
extern "C" void kernel_launch(void* const* d_in, const int* in_sizes, int n_in,
                              void* d_out, int out_size) {
    const float* x      = (const float*)d_in[0];
    const float* dl     = (const float*)d_in[1];
    const float* cpe_w  = (const float*)d_in[2];
    const float* cpe_b  = (const float*)d_in[3];
    const float* ln1_g  = (const float*)d_in[4];
    const float* ln1_b  = (const float*)d_in[5];
    const float* qkv_w  = (const float*)d_in[6];
    const float* proj_w = (const float*)d_in[7];
    const float* proj_b = (const float*)d_in[8];
    const float* dl_w1  = (const float*)d_in[9];
    const float* dl_b1  = (const float*)d_in[10];
    const float* dl_w2  = (const float*)d_in[11];
    const float* dl_b2  = (const float*)d_in[12];
    const float* w3     = (const float*)d_in[13];
    const float* b3     = (const float*)d_in[14];
    const float* w5     = (const float*)d_in[15];
    const float* b5     = (const float*)d_in[16];
    const float* w7     = (const float*)d_in[17];
    const float* b7     = (const float*)d_in[18];
    const float* ln2_g  = (const float*)d_in[19];
    const float* ln2_b  = (const float*)d_in[20];
    const float* fc1_w  = (const float*)d_in[21];
    const float* fc1_b  = (const float*)d_in[22];
    const float* fc2_w  = (const float*)d_in[23];
    const float* fc2_b  = (const float*)d_in[24];
    float* out = (float*)d_out;

    __half *p_x1h, *p_x2h, *p_qh, *p_kh, *p_vh, *p_curh, *p_atth, *p_hidh, *p_wth;
    cudaGetSymbolAddress((void**)&p_x1h,  g_x1h);
    cudaGetSymbolAddress((void**)&p_x2h,  g_x2h);
    cudaGetSymbolAddress((void**)&p_qh,   g_qh);
    cudaGetSymbolAddress((void**)&p_kh,   g_kh);
    cudaGetSymbolAddress((void**)&p_vh,   g_vh);
    cudaGetSymbolAddress((void**)&p_curh, g_curh);
    cudaGetSymbolAddress((void**)&p_atth, g_atth);
    cudaGetSymbolAddress((void**)&p_hidh, g_hidh);
    cudaGetSymbolAddress((void**)&p_wth,  g_wth);

    __half* qkvH  = p_wth;
    __half* projH = p_wth + 196608;
    __half* fc1H  = p_wth + 262144;
    __half* fc2H  = p_wth + 524288;

    const int GSM128 = 3 * (16384 + 16384);
    const int GSM64  = 3 * (16384 + 8192);
    cudaFuncSetAttribute((gemm_h<3,128>), cudaFuncAttributeMaxDynamicSharedMemorySize, GSM128);
    cudaFuncSetAttribute((gemm_h<2,128>), cudaFuncAttributeMaxDynamicSharedMemorySize, GSM128);
    cudaFuncSetAttribute((gemm_h<4,64>),  cudaFuncAttributeMaxDynamicSharedMemorySize, GSM64);
    cudaFuncSetAttribute((gemm_h<5,64>),  cudaFuncAttributeMaxDynamicSharedMemorySize, GSM64);

    // streams/events: 3 side streams, all forked from stream 0
    static cudaStream_t sS[3] = {nullptr, nullptr, nullptr};
    static cudaEvent_t  evFork = nullptr, evW = nullptr;
    static cudaEvent_t  evJ[3] = {nullptr, nullptr, nullptr};
    if (sS[0] == nullptr) {
        for (int i = 0; i < 3; i++) {
            cudaStreamCreateWithFlags(&sS[i], cudaStreamNonBlocking);
            cudaEventCreateWithFlags(&evJ[i], cudaEventDisableTiming);
        }
        cudaEventCreateWithFlags(&evFork, cudaEventDisableTiming);
        cudaEventCreateWithFlags(&evW, cudaEventDisableTiming);
    }

    const int QB  = 2;
    const int QBN = QB * NN;

    // fork side streams from stream 0 FIRST (legal capture origin)
    cudaEventRecord(evFork, 0);
    for (int i = 0; i < 3; i++) cudaStreamWaitEvent(sS[i], evFork, 0);

    // cpe_ln1 for all quarters runs concurrently with weight conversion
    cpe_ln1_kernel<<<QBN / 8, 128, 0, 0>>>(x, cpe_w, cpe_b, ln1_g, ln1_b, 0);
    cpe_ln1_kernel<<<QBN / 8, 128, 0, sS[0]>>>(x, cpe_w, cpe_b, ln1_g, ln1_b, (2 * NN) / 8);
    cpe_ln1_kernel<<<QBN / 8, 128, 0, sS[1]>>>(x, cpe_w, cpe_b, ln1_g, ln1_b, (4 * NN) / 8);
    cpe_ln1_kernel<<<QBN / 8, 128, 0, sS[2]>>>(x, cpe_w, cpe_b, ln1_g, ln1_b, (6 * NN) / 8);

    // weight conversion on stream 0, gates all GEMMs
    f2h_all<<<768, 256, 0, 0>>>(qkv_w, proj_w, fc1_w, fc2_w, p_wth);
    cudaEventRecord(evW, 0);
    for (int i = 0; i < 3; i++) cudaStreamWaitEvent(sS[i], evW, 0);

    auto rest = [&](cudaStream_t st, int b0) {
        size_t off = (size_t)b0 * NN;
        gemm_h<3,128><<<dim3(QKVW/128, QBN/128), 256, GSM128, st>>>(
            p_curh + off * CC, qkvH, p_qh + off * CC, QBN, QKVW, CC,
            nullptr, nullptr, p_kh + off * CC, p_vh + off * CC);
        kv_build_kernel<<<dim3(KSEG, QB), 256, 0, st>>>(b0);
        kv_norm_da_kernel<<<QB * NHEAD + 1, 1024, 0, st>>>(dl, dl_w1, dl_b1, dl_w2, dl_b2, b0, QB);
        attn_build_kernel<<<QB * NN / 8, 128, 0, st>>>(w3, b3, w5, b5, w7, b7, b0);
        gemm_h<4,64><<<dim3(CC/64, QBN/128), 256, GSM64, st>>>(
            p_atth + off * CC, projH, p_x2h + off * CC, QBN, CC, CC,
            proj_b, p_x1h + off * CC, nullptr, nullptr);
        ln2_kernel<<<QBN, 128, 0, st>>>(ln2_g, ln2_b, (int)off);
        gemm_h<2,128><<<dim3(MH/128, QBN/128), 256, GSM128, st>>>(
            p_curh + off * CC, fc1H, p_hidh + off * MH, QBN, MH, CC,
            fc1_b, nullptr, nullptr, nullptr);
        gemm_h<5,64><<<dim3(CC/64, QBN/128), 256, GSM64, st>>>(
            p_hidh + off * MH, fc2H, out + off * CC, QBN, CC, MH,
            fc2_b, p_x2h + off * CC, nullptr, nullptr);
    };

    rest((cudaStream_t)0, 0);
    rest(sS[0], 2);
    rest(sS[1], 4);
    rest(sS[2], 6);

    for (int i = 0; i < 3; i++) {
        cudaEventRecord(evJ[i], sS[i]);
        cudaStreamWaitEvent((cudaStream_t)0, evJ[i], 0);
    }
}

// round 16
// speedup vs baseline: 1.0567x; 1.0461x over previous
#include <cuda_runtime.h>
#include <cuda_fp16.h>
#include <stdint.h>
#include <math.h>

// ---------------- static problem shapes ----------------
#define BB    8
#define HH    56
#define WW    56
#define NN    (HH*WW)        // 3136
#define CC    256
#define NHEAD 8
#define CH    32
#define BN_TOT (BB*NN)       // 25088
#define QKVW  768
#define MH    1024
#define KSEG  98             // 32-token segments

// ---------------- scratch ----------------
__device__ __align__(16) __half g_x1h [BN_TOT*CC];
__device__ __align__(16) __half g_x2h [BN_TOT*CC];
__device__ __align__(16) __half g_qh  [BN_TOT*CC];
__device__ __align__(16) __half g_kh  [BN_TOT*CC];   // holds exp(k)
__device__ __align__(16) __half g_vh  [BN_TOT*CC];
__device__ __align__(16) __half g_curh[BN_TOT*CC];
__device__ __align__(16) __half g_atth[BN_TOT*CC];
__device__ __align__(16) __half g_hidh[BN_TOT*MH];
__device__ __align__(16) __half g_wth [786432];
__device__ float  g_kv  [64*CH*CH];
__device__ float  g_da  [BB*CC];
__device__ float  g_kvp [KSEG*64*CH*CH];
__device__ float  g_ksp [KSEG*64*CH];

// ---------------- helpers ----------------
__device__ __forceinline__ uint32_t smem_u32(const void* p){
    uint32_t a; asm("{.reg .u64 t; cvta.to.shared.u64 t, %1; cvt.u32.u64 %0, t;}":"=r"(a):"l"(p)); return a;
}
__device__ __forceinline__ void cp_async16(uint32_t dst, const void* src){
    asm volatile("cp.async.cg.shared.global [%0], [%1], 16;"::"r"(dst),"l"(src):"memory");
}
__device__ __forceinline__ void cp_commit(){ asm volatile("cp.async.commit_group;":::"memory"); }
template<int N> __device__ __forceinline__ void cp_wait(){ asm volatile("cp.async.wait_group %0;"::"n"(N):"memory"); }

__device__ __forceinline__ void ldsm4(uint32_t* r, uint32_t addr){
    asm volatile("ldmatrix.sync.aligned.m8n8.x4.shared.b16 {%0,%1,%2,%3}, [%4];"
        :"=r"(r[0]),"=r"(r[1]),"=r"(r[2]),"=r"(r[3]):"r"(addr));
}
__device__ __forceinline__ void ldsm4t(uint32_t* r, uint32_t addr){
    asm volatile("ldmatrix.sync.aligned.m8n8.x4.trans.shared.b16 {%0,%1,%2,%3}, [%4];"
        :"=r"(r[0]),"=r"(r[1]),"=r"(r[2]),"=r"(r[3]):"r"(addr));
}
__device__ __forceinline__ void mma_f16(float* d, const uint32_t* a, const uint32_t* b){
    asm volatile(
        "mma.sync.aligned.m16n8k16.row.col.f32.f16.f16.f32 "
        "{%0,%1,%2,%3}, {%4,%5,%6,%7}, {%8,%9}, {%0,%1,%2,%3};"
        : "+f"(d[0]),"+f"(d[1]),"+f"(d[2]),"+f"(d[3])
        : "r"(a[0]),"r"(a[1]),"r"(a[2]),"r"(a[3]),"r"(b[0]),"r"(b[1]));
}

__device__ __forceinline__ uint32_t aoff(int r, int q){
    return (uint32_t)((r << 7) + (((q ^ (r & 7)) & 7) << 4));
}
// unified B-stage swizzle: row stride = CB*16 bytes, XOR low 3 chunk bits with k&7
template<int CB>
__device__ __forceinline__ uint32_t boff(int k, int c){
    return (uint32_t)(k * (CB * 16) + (((c & ~7) | ((c & 7) ^ (k & 7)))) * 16);
}

// ---------------- all-weights fp32 -> half ----------------
__global__ void f2h_all(const float* __restrict__ a, const float* __restrict__ b,
                        const float* __restrict__ c, const float* __restrict__ d,
                        __half* __restrict__ dst){
    int i = (blockIdx.x * blockDim.x + threadIdx.x) * 4;
    const float* src; int off;
    if      (i < 196608) { src = a; off = 0; }
    else if (i < 262144) { src = b; off = 196608; }
    else if (i < 524288) { src = c; off = 262144; }
    else                 { src = d; off = 524288; }
    float4 v = *(const float4*)(src + (i - off));
    __half2 h0 = __floats2half2_rn(v.x, v.y);
    __half2 h1 = __floats2half2_rn(v.z, v.w);
    *(uint2*)(dst + i) = make_uint2(*(uint32_t*)&h0, *(uint32_t*)&h1);
}

// ---------------- CPE dw3x3 + residual + LN1, 8-token tiles ----------------
__global__ __launch_bounds__(128)
void cpe_ln1_kernel(const float* __restrict__ x,
                    const float* __restrict__ cpe_w,
                    const float* __restrict__ cpe_b,
                    const float* __restrict__ ln_g,
                    const float* __restrict__ ln_b, int blk0) {
    int blk = blk0 + blockIdx.x;
    int b   = blk / (NN / 8);
    int rem = blk % (NN / 8);
    int hh  = rem / (WW / 8);
    int ww0 = (rem % (WW / 8)) * 8;
    int t   = threadIdx.x;
    int c0  = t * 2;

    const float* xb = x + (size_t)b * NN * CC + c0;
    const float* w0 = cpe_w + c0 * 9;
    const float* w1 = w0 + 9;
    float w0r[9], w1r[9];
    #pragma unroll
    for (int j = 0; j < 9; j++) { w0r[j] = w0[j]; w1r[j] = w1[j]; }

    float cv0[8], cv1[8];
    float bias0 = cpe_b[c0], bias1 = cpe_b[c0 + 1];
    #pragma unroll
    for (int tok = 0; tok < 8; tok++) { cv0[tok] = bias0; cv1[tok] = bias1; }
    float xc0[8], xc1[8];

    #pragma unroll
    for (int dy = 0; dy < 3; dy++) {
        int y = hh - 1 + dy;
        bool yok = (unsigned)y < HH;
        #pragma unroll
        for (int xx = 0; xx < 10; xx++) {
            int gx = ww0 - 1 + xx;
            float2 xv = make_float2(0.f, 0.f);
            if (yok && (unsigned)gx < WW)
                xv = *(const float2*)(xb + (size_t)(y * WW + gx) * CC);
            if (dy == 1 && xx >= 1 && xx <= 8) { xc0[xx - 1] = xv.x; xc1[xx - 1] = xv.y; }
            #pragma unroll
            for (int tok = 0; tok < 8; tok++) {
                int j = xx - tok;
                if (j < 0 || j >= 3) continue;
                cv0[tok] += xv.x * w0r[dy * 3 + j];
                cv1[tok] += xv.y * w1r[dy * 3 + j];
            }
        }
    }

    size_t row0 = (size_t)b * NN + hh * WW + ww0;
    __shared__ float s1[128][9];
    __shared__ float s2[128][9];
    #pragma unroll
    for (int tok = 0; tok < 8; tok++) {
        cv0[tok] += xc0[tok];
        cv1[tok] += xc1[tok];
        *(__half2*)(g_x1h + (row0 + tok) * CC + c0) = __floats2half2_rn(cv0[tok], cv1[tok]);
        s1[t][tok] = cv0[tok] + cv1[tok];
        s2[t][tok] = cv0[tok] * cv0[tok] + cv1[tok] * cv1[tok];
    }
    __syncthreads();
    for (int off = 64; off > 0; off >>= 1) {
        if (t < off) {
            #pragma unroll
            for (int tok = 0; tok < 8; tok++) {
                s1[t][tok] += s1[t + off][tok];
                s2[t][tok] += s2[t + off][tok];
            }
        }
        __syncthreads();
    }
    float g0 = ln_g[c0], g1 = ln_g[c0 + 1];
    float bb0 = ln_b[c0], bb1 = ln_b[c0 + 1];
    #pragma unroll
    for (int tok = 0; tok < 8; tok++) {
        float mean = s1[0][tok] * (1.0f / CC);
        float var  = s2[0][tok] * (1.0f / CC) - mean * mean;
        float inv  = rsqrtf(var + 1e-5f);
        float o0 = (cv0[tok] - mean) * inv * g0 + bb0;
        float o1 = (cv1[tok] - mean) * inv * g1 + bb1;
        *(__half2*)(g_curh + (row0 + tok) * CC + c0) = __floats2half2_rn(o0, o1);
    }
}

// ---------------- fp16 tensor-core GEMM ----------------
// EPI 2: half C = gelu(acc+bias)
// EPI 3: qkv split all-half -> q, exp(k), v
// EPI 5: fp32 C = acc + bias + half-res          (fc2 -> out)
// EPI 6: proj + residual + fused LN2: x2h = acc+bias+x1h; curh = LN(x2)  (BN=256, BM=64)
template <int EPI, int BN, int BM>
__global__ __launch_bounds__(256)
void gemm_h(const __half* __restrict__ A, const __half* __restrict__ B,
            void* __restrict__ Cv, int M, int Nc, int K,
            const float* __restrict__ bias, const void* __restrict__ resv,
            __half* __restrict__ kh, __half* __restrict__ vh,
            const float* __restrict__ lng, const float* __restrict__ lnb,
            __half* __restrict__ cur) {
    constexpr int MWARPS = (BN == 128) ? 2 : ((BN == 64) ? 4 : 1);
    constexpr int MT     = BM / 16 / MWARPS;
    constexpr int CB     = BN / 8;
    constexpr int ASTB_  = BM * 128;
    constexpr int BSTB_  = 64 * BN * 2;
    constexpr int STGB_  = ASTB_ + BSTB_;

    extern __shared__ char smc[];
    uint32_t sb = smem_u32(smc);
    const int tid  = threadIdx.x;
    const int lane = tid & 31;
    const int w    = tid >> 5;
    const int wm   = w % MWARPS;
    const int wn   = w / MWARPS;
    const int g    = lane >> 2;
    const int qt   = lane & 3;
    const int sub  = lane >> 3;
    const int rin  = lane & 7;

    const __half* Ab = A + (size_t)blockIdx.y * BM * K;
    const __half* Bb = B + (size_t)blockIdx.x * BN;
    const int S = K >> 6;

    auto load = [&](int s, int buf) {
        uint32_t ab  = sb + buf * STGB_;
        uint32_t bbs = ab + ASTB_;
        const __half* Ac = Ab + (s << 6);
        const __half* Bc = Bb + (size_t)(s << 6) * Nc;
        #pragma unroll
        for (int r2 = 0; r2 < BM / 32; r2++) {
            int idx = tid + (r2 << 8);
            int row = idx >> 3, q = idx & 7;
            cp_async16(ab + aoff(row, q), Ac + (size_t)row * K + (q << 3));
        }
        #pragma unroll
        for (int r2 = 0; r2 < BN / 32; r2++) {
            int idx = tid + (r2 << 8);
            int k = idx / CB, c = idx % CB;
            cp_async16(bbs + boff<CB>(k, c), Bc + (size_t)k * Nc + (c << 3));
        }
        cp_commit();
    };

    float acc[MT][4][4];
    #pragma unroll
    for (int i = 0; i < MT; i++)
        #pragma unroll
        for (int j = 0; j < 4; j++)
            #pragma unroll
            for (int q = 0; q < 4; q++) acc[i][j][q] = 0.f;

    load(0, 0);
    load(1, 1);

    for (int s = 0; s < S; s++) {
        int buf = s % 3;
        if (s + 1 < S) cp_wait<1>(); else cp_wait<0>();
        __syncthreads();
        if (s + 2 < S) load(s + 2, (s + 2) % 3);

        uint32_t ab  = sb + buf * STGB_;
        uint32_t bbs = ab + ASTB_;
        #pragma unroll
        for (int ks = 0; ks < 4; ks++) {
            uint32_t af[MT][4];
            #pragma unroll
            for (int mt = 0; mt < MT; mt++) {
                int m = wm * (MT * 16) + mt * 16 + (sub & 1) * 8 + rin;
                int q = ks * 2 + (sub >> 1);
                ldsm4(af[mt], ab + aoff(m, q));
            }
            uint32_t bf[2][4];
            #pragma unroll
            for (int p = 0; p < 2; p++) {
                int k = ks * 16 + (sub & 1) * 8 + rin;
                int c = wn * 4 + p * 2 + (sub >> 1);
                ldsm4t(bf[p], bbs + boff<CB>(k, c));
            }
            #pragma unroll
            for (int mt = 0; mt < MT; mt++)
                #pragma unroll
                for (int nt = 0; nt < 4; nt++)
                    mma_f16(acc[mt][nt], af[mt], &bf[nt >> 1][(nt & 1) * 2]);
        }
        __syncthreads();
    }

    if (EPI == 6) {
        // pass 1: x2 = acc + bias + x1h (half res); store x2h; row partial sums
        float psum[MT][2], psq[MT][2];
        #pragma unroll
        for (int mt = 0; mt < MT; mt++) { psum[mt][0]=psum[mt][1]=psq[mt][0]=psq[mt][1]=0.f; }
        #pragma unroll
        for (int mt = 0; mt < MT; mt++) {
            #pragma unroll
            for (int nt = 0; nt < 4; nt++) {
                int col = wn * 32 + nt * 8 + qt * 2;
                #pragma unroll
                for (int h = 0; h < 2; h++) {
                    int lrow = mt * 16 + g + h * 8;
                    int row  = blockIdx.y * BM + lrow;
                    float2 r2 = __half22float2(*(const __half2*)((const __half*)resv + (size_t)row * Nc + col));
                    float v0 = acc[mt][nt][h * 2 + 0] + bias[col]     + r2.x;
                    float v1 = acc[mt][nt][h * 2 + 1] + bias[col + 1] + r2.y;
                    acc[mt][nt][h * 2 + 0] = v0;
                    acc[mt][nt][h * 2 + 1] = v1;
                    *(__half2*)((__half*)Cv + (size_t)row * Nc + col) = __floats2half2_rn(v0, v1);
                    psum[mt][h] += v0 + v1;
                    psq[mt][h]  += v0 * v0 + v1 * v1;
                }
            }
        }
        float* red1 = (float*)smc;          // [64][33]
        float* red2 = red1 + 64 * 33;       // [64][33]
        #pragma unroll
        for (int mt = 0; mt < MT; mt++)
            #pragma unroll
            for (int h = 0; h < 2; h++) {
                int lrow = mt * 16 + g + h * 8;
                red1[lrow * 33 + w * 4 + qt] = psum[mt][h];
                red2[lrow * 33 + w * 4 + qt] = psq[mt][h];
            }
        __syncthreads();
        if (tid < 64) {
            float s = 0.f, q = 0.f;
            #pragma unroll
            for (int j = 0; j < 32; j++) { s += red1[tid * 33 + j]; q += red2[tid * 33 + j]; }
            float mean = s * (1.0f / CC);
            float var  = q * (1.0f / CC) - mean * mean;
            red1[tid * 33 + 32] = mean;
            red2[tid * 33 + 32] = rsqrtf(var + 1e-5f);
        }
        __syncthreads();
        #pragma unroll
        for (int mt = 0; mt < MT; mt++) {
            #pragma unroll
            for (int nt = 0; nt < 4; nt++) {
                int col = wn * 32 + nt * 8 + qt * 2;
                float gg0 = lng[col], gg1 = lng[col + 1];
                float bb0 = lnb[col], bb1 = lnb[col + 1];
                #pragma unroll
                for (int h = 0; h < 2; h++) {
                    int lrow = mt * 16 + g + h * 8;
                    int row  = blockIdx.y * BM + lrow;
                    float mean = red1[lrow * 33 + 32];
                    float inv  = red2[lrow * 33 + 32];
                    float o0 = (acc[mt][nt][h * 2 + 0] - mean) * inv * gg0 + bb0;
                    float o1 = (acc[mt][nt][h * 2 + 1] - mean) * inv * gg1 + bb1;
                    *(__half2*)(cur + (size_t)row * Nc + col) = __floats2half2_rn(o0, o1);
                }
            }
        }
        return;
    }

    #pragma unroll
    for (int mt = 0; mt < MT; mt++) {
        int row0 = blockIdx.y * BM + wm * (MT * 16) + mt * 16 + g;
        #pragma unroll
        for (int nt = 0; nt < 4; nt++) {
            int col = blockIdx.x * BN + wn * 32 + nt * 8 + qt * 2;
            #pragma unroll
            for (int h = 0; h < 2; h++) {
                int row = row0 + h * 8;
                float v0 = acc[mt][nt][h * 2 + 0];
                float v1 = acc[mt][nt][h * 2 + 1];
                if (EPI == 2) {
                    v0 += bias[col];
                    v1 += bias[col + 1];
                    v0 = 0.5f * v0 * (1.0f + erff(v0 * 0.70710678118654752f));
                    v1 = 0.5f * v1 * (1.0f + erff(v1 * 0.70710678118654752f));
                    *(__half2*)((__half*)Cv + (size_t)row * Nc + col) = __floats2half2_rn(v0, v1);
                } else if (EPI == 3) {
                    if (col < CC) {
                        *(__half2*)((__half*)Cv + (size_t)row * CC + col) = __floats2half2_rn(v0, v1);
                    } else if (col < 2 * CC) {
                        *(__half2*)(kh + (size_t)row * CC + (col - CC)) =
                            __floats2half2_rn(expf(v0), expf(v1));
                    } else {
                        *(__half2*)(vh + (size_t)row * CC + (col - 2 * CC)) = __floats2half2_rn(v0, v1);
                    }
                } else { // EPI 5
                    float2 r2 = __half22float2(*(const __half2*)((const __half*)resv + (size_t)row * Nc + col));
                    v0 += bias[col]     + r2.x;
                    v1 += bias[col + 1] + r2.y;
                    *(float2*)((float*)Cv + (size_t)row * Nc + col) = make_float2(v0, v1);
                }
            }
        }
    }
}

// ---------------- kv partials ----------------
__global__ __launch_bounds__(256)
void kv_build_kernel(int b0) {
    int seg = blockIdx.x;
    int b   = b0 + blockIdx.y;
    int t   = threadIdx.x;
    int head = t >> 5, i = t & 31;

    __shared__ __align__(16) float ksf[16][256];
    __shared__ __align__(16) float vsf[16][256];

    float acc[32];
    #pragma unroll
    for (int j = 0; j < 32; j++) acc[j] = 0.f;
    float ssum = 0.f;

    const __half* kb = g_kh + ((size_t)b * NN + seg * 32) * CC;
    const __half* vb = g_vh + ((size_t)b * NN + seg * 32) * CC;

    for (int tile = 0; tile < 2; tile++) {
        #pragma unroll
        for (int r2 = 0; r2 < 2; r2++) {
            int idx = t + (r2 << 8);
            int row = idx >> 5, c8 = (idx & 31) << 3;
            size_t goff = (size_t)(tile * 16 + row) * CC + c8;
            uint4 kv4 = *(const uint4*)(kb + goff);
            uint4 vv4 = *(const uint4*)(vb + goff);
            const __half2* kp = (const __half2*)&kv4;
            const __half2* vp = (const __half2*)&vv4;
            #pragma unroll
            for (int p = 0; p < 4; p++) {
                float2 kf = __half22float2(kp[p]);
                float2 vf = __half22float2(vp[p]);
                ksf[row][c8 + p * 2]     = kf.x;
                ksf[row][c8 + p * 2 + 1] = kf.y;
                vsf[row][c8 + p * 2]     = vf.x;
                vsf[row][c8 + p * 2 + 1] = vf.y;
            }
        }
        __syncthreads();
        #pragma unroll
        for (int nn = 0; nn < 16; nn++) {
            float e = ksf[nn][head * CH + i];
            ssum += e;
            const float* vrow = &vsf[nn][head * CH];
            #pragma unroll
            for (int j4 = 0; j4 < 8; j4++) {
                float4 v4 = *(const float4*)(vrow + j4 * 4);
                acc[j4 * 4 + 0] += e * v4.x;
                acc[j4 * 4 + 1] += e * v4.y;
                acc[j4 * 4 + 2] += e * v4.z;
                acc[j4 * 4 + 3] += e * v4.w;
            }
        }
        __syncthreads();
    }

    int bh = b * NHEAD + head;
    float* kvp = g_kvp + ((size_t)(seg * 64 + bh) * CH + i) * CH;
    #pragma unroll
    for (int j4 = 0; j4 < 8; j4++)
        *(float4*)(kvp + j4 * 4) = make_float4(acc[j4*4], acc[j4*4+1], acc[j4*4+2], acc[j4*4+3]);
    g_ksp[(seg * 64 + bh) * CH + i] = ssum;
}

// ---------------- kv reduce+normalize + domain gating, per quarter ----------------
__global__ void kv_norm_da_kernel(const float* __restrict__ dl,
                                  const float* __restrict__ w1, const float* __restrict__ b1,
                                  const float* __restrict__ w2, const float* __restrict__ b2,
                                  int b0, int nb) {
    int nbh = nb * NHEAD;
    if ((int)blockIdx.x < nbh) {
        int bh = b0 * NHEAD + blockIdx.x;
        int t = threadIdx.x;
        int i = t >> 5, j = t & 31;
        float s = 0.f, kvv = 0.f;
        for (int p = 0; p < KSEG; p++) {
            s   += g_ksp[(p * 64 + bh) * CH + i];
            kvv += g_kvp[((size_t)(p * 64 + bh) * CH + i) * CH + j];
        }
        g_kv[((size_t)bh * CH + i) * CH + j] = kvv / s;
        return;
    }
    int t = threadIdx.x;
    if (t >= 256) return;
    __shared__ float hid[128];
    __shared__ float outb[4 * CC];
    for (int bi = 0; bi < nb; bi++) {
        int b = b0 + bi;
        if (t < 128) {
            float a = b1[t];
            #pragma unroll
            for (int k = 0; k < 4; k++) a += dl[b * 4 + k] * w1[k * 128 + t];
            hid[t] = fmaxf(a, 0.f);
        }
        asm volatile("bar.sync 1, 256;" ::: "memory");
        float o = b2[t];
        for (int i = 0; i < 128; i++) o += hid[i] * w2[i * CC + t];
        outb[bi * CC + t] = o;
        asm volatile("bar.sync 1, 256;" ::: "memory");
    }
    if (t < nb * 32) {
        int bb = t >> 5;
        int ch = t & 31;
        float m = -1e30f;
        #pragma unroll
        for (int hd = 0; hd < NHEAD; hd++)
            m = fmaxf(m, outb[bb * CC + hd * CH + ch]);
        float e[NHEAD], s = 0.f;
        #pragma unroll
        for (int hd = 0; hd < NHEAD; hd++) {
            e[hd] = expf(outb[bb * CC + hd * CH + ch] - m);
            s += e[hd];
        }
        float inv = 1.0f / s;
        #pragma unroll
        for (int hd = 0; hd < NHEAD; hd++)
            g_da[(b0 + bb) * CC + hd * CH + ch] = e[hd] * inv;
    }
}

// ---------------- conv-RPE inner ----------------
template<int KSZ>
__device__ __forceinline__ void conv8(float* cv0, float* cv1,
                                      const __half* vb, const float* wb0, const float* wb1,
                                      int hh, int ww0) {
    constexpr int RAD = KSZ / 2;
    #pragma unroll
    for (int dy = 0; dy < KSZ; dy++) {
        int y = hh - RAD + dy;
        if ((unsigned)y >= HH) continue;
        float w0r[KSZ], w1r[KSZ];
        #pragma unroll
        for (int j = 0; j < KSZ; j++) {
            w0r[j] = wb0[dy * KSZ + j];
            w1r[j] = wb1[dy * KSZ + j];
        }
        const __half* vrow = vb + (size_t)(y * WW) * CC;
        #pragma unroll
        for (int xx = 0; xx < 8 + 2 * RAD; xx++) {
            int gx = ww0 - RAD + xx;
            if ((unsigned)gx >= WW) continue;
            float2 vf = __half22float2(*(const __half2*)(vrow + (size_t)gx * CC));
            #pragma unroll
            for (int tok = 0; tok < 8; tok++) {
                int j = xx - tok;
                if (j < 0 || j >= KSZ) continue;
                cv0[tok] += vf.x * w0r[j];
                cv1[tok] += vf.y * w1r[j];
            }
        }
    }
}

// ---------------- factor-att + conv-RPE + gating, 8 tokens per block ----------------
__global__ __launch_bounds__(128)
void attn_build_kernel(const float* __restrict__ w3, const float* __restrict__ b3,
                       const float* __restrict__ w5, const float* __restrict__ b5,
                       const float* __restrict__ w7, const float* __restrict__ b7,
                       int b0) {
    int blk = blockIdx.x;
    int b   = b0 + blk / (NN / 8);
    int rem = blk % (NN / 8);
    int hh  = rem / (WW / 8);
    int ww0 = (rem % (WW / 8)) * 8;
    int t   = threadIdx.x;
    int c0  = t * 2;
    int head = c0 >> 5;
    int ch0  = c0 & 31;

    __shared__ float qs[8][CC];
    size_t row0 = (size_t)b * NN + hh * WW + ww0;
    #pragma unroll
    for (int tok = 0; tok < 8; tok++) {
        float2 qv = __half22float2(*(const __half2*)(g_qh + (row0 + tok) * CC + c0));
        *(float2*)&qs[tok][c0] = qv;
    }
    __syncthreads();

    float fa0[8], fa1[8];
    #pragma unroll
    for (int tok = 0; tok < 8; tok++) { fa0[tok] = 0.f; fa1[tok] = 0.f; }
    const float* kvb = g_kv + (size_t)(b * NHEAD + head) * CH * CH;
    #pragma unroll
    for (int k2 = 0; k2 < CH; k2++) {
        float2 kv2 = *(const float2*)(kvb + k2 * CH + ch0);
        #pragma unroll
        for (int tok = 0; tok < 8; tok++) {
            float qv = qs[tok][head * CH + k2];
            fa0[tok] += qv * kv2.x;
            fa1[tok] += qv * kv2.y;
        }
    }

    float cv0[8], cv1[8];
    const __half* vb = g_vh + (size_t)b * NN * CC + c0;
    if (c0 < 64) {
        #pragma unroll
        for (int tok = 0; tok < 8; tok++) { cv0[tok] = b3[c0]; cv1[tok] = b3[c0 + 1]; }
        conv8<3>(cv0, cv1, vb, w3 + c0 * 9, w3 + (c0 + 1) * 9, hh, ww0);
    } else if (c0 < 160) {
        #pragma unroll
        for (int tok = 0; tok < 8; tok++) { cv0[tok] = b5[c0 - 64]; cv1[tok] = b5[c0 - 63]; }
        conv8<5>(cv0, cv1, vb, w5 + (c0 - 64) * 25, w5 + (c0 - 63) * 25, hh, ww0);
    } else {
        #pragma unroll
        for (int tok = 0; tok < 8; tok++) { cv0[tok] = b7[c0 - 160]; cv1[tok] = b7[c0 - 159]; }
        conv8<7>(cv0, cv1, vb, w7 + (c0 - 160) * 49, w7 + (c0 - 159) * 49, hh, ww0);
    }

    float2 da2 = *(const float2*)(g_da + b * CC + c0);
    const float scale = 0.17677669529663687f;
    #pragma unroll
    for (int tok = 0; tok < 8; tok++) {
        float q0 = qs[tok][c0], q1 = qs[tok][c0 + 1];
        float o0 = da2.x * (fa0[tok] * scale + q0 * cv0[tok]);
        float o1 = da2.y * (fa1[tok] * scale + q1 * cv1[tok]);
        *(__half2*)(g_atth + (row0 + tok) * CC + c0) = __floats2half2_rn(o0, o1);
    }
}

// ---------------- launch ----------------
extern "C" void kernel_launch(void* const* d_in, const int* in_sizes, int n_in,
                              void* d_out, int out_size) {
    const float* x      = (const float*)d_in[0];
    const float* dl     = (const float*)d_in[1];
    const float* cpe_w  = (const float*)d_in[2];
    const float* cpe_b  = (const float*)d_in[3];
    const float* ln1_g  = (const float*)d_in[4];
    const float* ln1_b  = (const float*)d_in[5];
    const float* qkv_w  = (const float*)d_in[6];
    const float* proj_w = (const float*)d_in[7];
    const float* proj_b = (const float*)d_in[8];
    const float* dl_w1  = (const float*)d_in[9];
    const float* dl_b1  = (const float*)d_in[10];
    const float* dl_w2  = (const float*)d_in[11];
    const float* dl_b2  = (const float*)d_in[12];
    const float* w3     = (const float*)d_in[13];
    const float* b3     = (const float*)d_in[14];
    const float* w5     = (const float*)d_in[15];
    const float* b5     = (const float*)d_in[16];
    const float* w7     = (const float*)d_in[17];
    const float* b7     = (const float*)d_in[18];
    const float* ln2_g  = (const float*)d_in[19];
    const float* ln2_b  = (const float*)d_in[20];
    const float* fc1_w  = (const float*)d_in[21];
    const float* fc1_b  = (const float*)d_in[22];
    const float* fc2_w  = (const float*)d_in[23];
    const float* fc2_b  = (const float*)d_in[24];
    float* out = (float*)d_out;

    __half *p_x1h, *p_x2h, *p_qh, *p_kh, *p_vh, *p_curh, *p_atth, *p_hidh, *p_wth;
    cudaGetSymbolAddress((void**)&p_x1h,  g_x1h);
    cudaGetSymbolAddress((void**)&p_x2h,  g_x2h);
    cudaGetSymbolAddress((void**)&p_qh,   g_qh);
    cudaGetSymbolAddress((void**)&p_kh,   g_kh);
    cudaGetSymbolAddress((void**)&p_vh,   g_vh);
    cudaGetSymbolAddress((void**)&p_curh, g_curh);
    cudaGetSymbolAddress((void**)&p_atth, g_atth);
    cudaGetSymbolAddress((void**)&p_hidh, g_hidh);
    cudaGetSymbolAddress((void**)&p_wth,  g_wth);

    __half* qkvH  = p_wth;
    __half* projH = p_wth + 196608;
    __half* fc1H  = p_wth + 262144;
    __half* fc2H  = p_wth + 524288;

    const int GSM128 = 3 * (16384 + 16384);
    const int GSM64  = 3 * (16384 + 8192);
    const int GSM256 = 3 * (8192 + 32768);   // 122880 (BM=64, BN=256)
    cudaFuncSetAttribute((gemm_h<3,128,128>), cudaFuncAttributeMaxDynamicSharedMemorySize, GSM128);
    cudaFuncSetAttribute((gemm_h<2,128,128>), cudaFuncAttributeMaxDynamicSharedMemorySize, GSM128);
    cudaFuncSetAttribute((gemm_h<5,64,128>),  cudaFuncAttributeMaxDynamicSharedMemorySize, GSM64);
    cudaFuncSetAttribute((gemm_h<6,256,64>),  cudaFuncAttributeMaxDynamicSharedMemorySize, GSM256);

    // streams/events: 3 side streams, all forked from stream 0
    static cudaStream_t sS[3] = {nullptr, nullptr, nullptr};
    static cudaEvent_t  evFork = nullptr, evW = nullptr;
    static cudaEvent_t  evJ[3] = {nullptr, nullptr, nullptr};
    if (sS[0] == nullptr) {
        for (int i = 0; i < 3; i++) {
            cudaStreamCreateWithFlags(&sS[i], cudaStreamNonBlocking);
            cudaEventCreateWithFlags(&evJ[i], cudaEventDisableTiming);
        }
        cudaEventCreateWithFlags(&evFork, cudaEventDisableTiming);
        cudaEventCreateWithFlags(&evW, cudaEventDisableTiming);
    }

    const int QB  = 2;
    const int QBN = QB * NN;

    // fork side streams from stream 0 FIRST (legal capture origin)
    cudaEventRecord(evFork, 0);
    for (int i = 0; i < 3; i++) cudaStreamWaitEvent(sS[i], evFork, 0);

    // cpe_ln1 for all quarters runs concurrently with weight conversion
    cpe_ln1_kernel<<<QBN / 8, 128, 0, 0>>>(x, cpe_w, cpe_b, ln1_g, ln1_b, 0);
    cpe_ln1_kernel<<<QBN / 8, 128, 0, sS[0]>>>(x, cpe_w, cpe_b, ln1_g, ln1_b, (2 * NN) / 8);
    cpe_ln1_kernel<<<QBN / 8, 128, 0, sS[1]>>>(x, cpe_w, cpe_b, ln1_g, ln1_b, (4 * NN) / 8);
    cpe_ln1_kernel<<<QBN / 8, 128, 0, sS[2]>>>(x, cpe_w, cpe_b, ln1_g, ln1_b, (6 * NN) / 8);

    // weight conversion on stream 0, gates all GEMMs
    f2h_all<<<768, 256, 0, 0>>>(qkv_w, proj_w, fc1_w, fc2_w, p_wth);
    cudaEventRecord(evW, 0);
    for (int i = 0; i < 3; i++) cudaStreamWaitEvent(sS[i], evW, 0);

    auto rest = [&](cudaStream_t st, int b0) {
        size_t off = (size_t)b0 * NN;
        gemm_h<3,128,128><<<dim3(QKVW/128, QBN/128), 256, GSM128, st>>>(
            p_curh + off * CC, qkvH, p_qh + off * CC, QBN, QKVW, CC,
            nullptr, nullptr, p_kh + off * CC, p_vh + off * CC, nullptr, nullptr, nullptr);
        kv_build_kernel<<<dim3(KSEG, QB), 256, 0, st>>>(b0);
        kv_norm_da_kernel<<<QB * NHEAD + 1, 1024, 0, st>>>(dl, dl_w1, dl_b1, dl_w2, dl_b2, b0, QB);
        attn_build_kernel<<<QB * NN / 8, 128, 0, st>>>(w3, b3, w5, b5, w7, b7, b0);
        // proj + residual + fused LN2 (writes x2h and curh)
        gemm_h<6,256,64><<<dim3(1, QBN/64), 256, GSM256, st>>>(
            p_atth + off * CC, projH, p_x2h + off * CC, QBN, CC, CC,
            proj_b, p_x1h + off * CC, nullptr, nullptr, ln2_g, ln2_b, p_curh + off * CC);
        gemm_h<2,128,128><<<dim3(MH/128, QBN/128), 256, GSM128, st>>>(
            p_curh + off * CC, fc1H, p_hidh + off * MH, QBN, MH, CC,
            fc1_b, nullptr, nullptr, nullptr, nullptr, nullptr, nullptr);
        gemm_h<5,64,128><<<dim3(CC/64, QBN/128), 256, GSM64, st>>>(
            p_hidh + off * MH, fc2H, out + off * CC, QBN, CC, MH,
            fc2_b, p_x2h + off * CC, nullptr, nullptr, nullptr, nullptr, nullptr);
    };

    rest((cudaStream_t)0, 0);
    rest(sS[0], 2);
    rest(sS[1], 4);
    rest(sS[2], 6);

    for (int i = 0; i < 3; i++) {
        cudaEventRecord(evJ[i], sS[i]);
        cudaStreamWaitEvent((cudaStream_t)0, evJ[i], 0);
    }
}